// round 13
// baseline (speedup 1.0000x reference)
#include <cuda_runtime.h>
#include <math.h>
#include <stdint.h>

static const int NN   = 4096;
static const int MEDG = 8192;
static const int NNZ  = 65536;
static const int NB   = 64;
static const int NT   = 64;   // NN/NB
static const int KSEL = 4096;
static const double SHIFT = 8.0;

// ---------------- static device scratch ----------------
static __device__ double   g_B[(size_t)NN * NN];      // matrix -> Cholesky L
static __device__ double   g_X[(size_t)NN * NN];      // L^{-1} (block lower)
static __device__ double   g_T[(size_t)2048 * 2048];  // recursive trinv temp
static __device__ double   g_Dinv[NT][NB][NB];        // inverses of diag blocks
static __device__ unsigned g_bitmap[((size_t)NN * MEDG) / 32];
static __device__ int      g_deg[NN];
static __device__ int      g_de[MEDG];
static __device__ int      g_off[MEDG + 1];
static __device__ int      g_cursor[MEDG];
static __device__ int      g_counts[MEDG];
static __device__ unsigned char g_owner[NNZ];
static __device__ int      g_nodelist[NNZ];
static __device__ float    g_deinv[MEDG];
static __device__ double   g_sumB;
static __device__ float    g_diagf[NN];
static __device__ float    g_edgesum[MEDG];
static __device__ float    g_probs[MEDG];

// ---------------- setup ----------------
__global__ void k_zero() {
    size_t i = (size_t)blockIdx.x * blockDim.x + threadIdx.x;
    size_t stride = (size_t)gridDim.x * blockDim.x;
    size_t nw = ((size_t)NN * MEDG) / 32;
    for (size_t w = i; w < nw; w += stride) g_bitmap[w] = 0u;
    for (size_t w = i; w < MEDG; w += stride) {
        g_de[w] = 0; g_cursor[w] = 0; g_counts[w] = 0; g_edgesum[w] = 0.0f;
    }
    for (size_t w = i; w < NN; w += stride) g_deg[w] = 0;
    if (i == 0) g_sumB = 0.0;
}

__global__ void k_pairs(const int* __restrict__ V, const int* __restrict__ E) {
    int i = blockIdx.x * blockDim.x + threadIdx.x;
    if (i >= NNZ) return;
    int v = V[i], e = E[i];
    atomicAdd(&g_counts[e], 1);
    size_t bit = (size_t)v * MEDG + e;
    unsigned mask = 1u << (bit & 31);
    unsigned old = atomicOr(&g_bitmap[bit >> 5], mask);
    if (!(old & mask)) {
        g_owner[i] = 1;
        atomicAdd(&g_de[e], 1);
        atomicAdd(&g_deg[v], 1);
    } else g_owner[i] = 0;
}

__global__ void k_scan() {
    __shared__ int part[1024];
    int t = threadIdx.x;
    int s = 0;
    for (int j = 0; j < 8; j++) s += g_de[t * 8 + j];
    part[t] = s;
    __syncthreads();
    if (t == 0) {
        int acc = 0;
        for (int i = 0; i < 1024; i++) { int tmp = part[i]; part[i] = acc; acc += tmp; }
        g_off[MEDG] = acc;
    }
    __syncthreads();
    int acc = part[t];
    for (int j = 0; j < 8; j++) { g_off[t * 8 + j] = acc; acc += g_de[t * 8 + j]; }
    for (int j = t; j < MEDG; j += 1024)
        g_deinv[j] = 1.0f / ((float)g_de[j] + 1e-8f);
}

__global__ void k_nodelist(const int* __restrict__ V, const int* __restrict__ E) {
    int i = blockIdx.x * blockDim.x + threadIdx.x;
    if (i >= NNZ || !g_owner[i]) return;
    int e = E[i];
    int pos = g_off[e] + atomicAdd(&g_cursor[e], 1);
    g_nodelist[pos] = V[i];
}

__global__ void k_fillB() {
    const double SON = SHIFT / (double)NN;
    size_t total = (size_t)NN * NN;
    size_t stride = (size_t)gridDim.x * blockDim.x;
    for (size_t idx = (size_t)blockIdx.x * blockDim.x + threadIdx.x; idx < total; idx += stride) {
        int i = (int)(idx >> 12), j = (int)(idx & (NN - 1));
        double v = SON;
        if (i == j) v += (double)g_deg[i] + (double)1e-3f;
        g_B[idx] = v;
    }
}

__global__ void k_scatter() {
    int e = blockIdx.x;
    int d = g_de[e];
    if (d == 0) return;
    int off = g_off[e];
    double w = -(double)g_deinv[e];
    for (int t = threadIdx.x; t < d * d; t += blockDim.x) {
        int u = g_nodelist[off + t / d];
        int v = g_nodelist[off + t % d];
        atomicAdd(&g_B[(size_t)u * NN + v], w);
    }
}

__global__ void k_sumB() {
    __shared__ double sh[256];
    double s = 0.0;
    size_t total = (size_t)NN * NN;
    size_t stride = (size_t)gridDim.x * blockDim.x;
    for (size_t idx = (size_t)blockIdx.x * blockDim.x + threadIdx.x; idx < total; idx += stride)
        s += g_B[idx];
    sh[threadIdx.x] = s;
    __syncthreads();
    for (int o = 128; o; o >>= 1) { if (threadIdx.x < o) sh[threadIdx.x] += sh[threadIdx.x + o]; __syncthreads(); }
    if (threadIdx.x == 0) atomicAdd(&g_sumB, sh[0]);
}

// ---------------- Cholesky diag block: factor + triangular inverse ----------------
__global__ void k_potrf_dinv(int kb) {
    extern __shared__ double sh[];
    double (*a)[NB + 1]    = (double (*)[NB + 1])sh;
    double (*minv)[NB + 1] = (double (*)[NB + 1])(sh + NB * (NB + 1));
    __shared__ double red[4][NB];
    int t = threadIdx.x;
    size_t base = ((size_t)kb * NB) * NN + (size_t)kb * NB;
    for (int idx = t; idx < NB * NB; idx += 256) {
        int r = idx >> 6, c = idx & 63;
        a[r][c] = g_B[base + (size_t)r * NN + c];
    }
    __syncthreads();
    for (int j = 0; j < NB; j++) {
        if (t == 0) a[j][j] = sqrt(a[j][j]);
        __syncthreads();
        double piv = a[j][j];
        for (int r = j + 1 + t; r < NB; r += 256) a[r][j] /= piv;
        __syncthreads();
        int W = NB - 1 - j;
        for (int idx = t; idx < W * W; idx += 256) {
            int r = j + 1 + idx / W, c = j + 1 + idx % W;
            if (c <= r) a[r][c] -= a[r][j] * a[c][j];
        }
        __syncthreads();
    }
    for (int idx = t; idx < NB * NB; idx += 256) {
        int r = idx >> 6, c = idx & 63;
        if (c <= r) g_B[base + (size_t)r * NN + c] = a[r][c];
    }
    for (int idx = t; idx < NB * NB; idx += 256)
        minv[idx >> 6][idx & 63] = ((idx >> 6) == (idx & 63)) ? 1.0 : 0.0;
    __syncthreads();
    int c = t & 63, p = t >> 6;
    for (int r = 0; r < NB; r++) {
        double part = 0.0;
        for (int k = p; k < r; k += 4) part += a[r][k] * minv[k][c];
        red[p][c] = part;
        __syncthreads();
        if (t < NB) {
            double s2 = red[0][t] + red[1][t] + red[2][t] + red[3][t];
            minv[r][t] = (minv[r][t] - s2) / a[r][r];
        }
        __syncthreads();
    }
    size_t xbase = ((size_t)kb * NB) * NN + (size_t)kb * NB;
    for (int idx = t; idx < NB * NB; idx += 256) {
        int r = idx >> 6, cc = idx & 63;
        double v = minv[r][cc];
        g_Dinv[kb][r][cc] = v;
        g_X[xbase + (size_t)r * NN + cc] = v;
    }
}

// ---------------- cp.async helpers ----------------
__device__ __forceinline__ void cpa8(uint32_t dst, const double* src) {
    asm volatile("cp.async.ca.shared.global [%0], [%1], 8;" :: "r"(dst), "l"(src));
}
__device__ __forceinline__ void cp_commit() {
    asm volatile("cp.async.commit_group;");
}
template<int N>
__device__ __forceinline__ void cp_wait() {
    asm volatile("cp.async.wait_group %0;" :: "n"(N));
}

// ======== 64x64 core (128 thr, 8x4 micro, 3-stage cp.async, 1 sync/chunk) ========
// Buffers: sA/sB[3][16][64] (48KB static total). Chunk c lives in buffer c%3.
// Per iter: wait<1> (chunk c landed) -> sync -> issue chunk c+2 (empty commit
// if past end, keeping group counts uniform) -> compute chunk c.
// Buffer-reuse safety: writes to buf (c+2)%3 == (c-1)%3 are issued after the
// sync at iter c, which every warp reaches only after finishing its reads of
// that buffer during compute at iter c-1.
template<int BT>
__device__ __forceinline__ void gemm_pipe(
    const double* __restrict__ Ag, size_t lda,
    const double* __restrict__ Bg, size_t ldb,
    int nc, double acc[8][4], int tid, int tx, int ty)
{
    __shared__ double sA[3][16][64], sB[3][16][64];
    int ka = tid & 15, ra0 = tid >> 4;       // A staging: col ka, rows ra0+8q
    int kb0 = tid >> 6, cb = tid & 63;       // B staging (BT=0): rows kb0+2q, col cb
    uint32_t aBase[3], bBase[3];
#pragma unroll
    for (int b = 0; b < 3; b++) {
        aBase[b] = (uint32_t)__cvta_generic_to_shared(&sA[b][ka][ra0]);
        if (BT) bBase[b] = (uint32_t)__cvta_generic_to_shared(&sB[b][ka][ra0]);
        else    bBase[b] = (uint32_t)__cvta_generic_to_shared(&sB[b][kb0][cb]);
    }
    // prologue: chunks 0 and 1 (uniform commits)
#pragma unroll
    for (int c0 = 0; c0 < 2; c0++) {
        if (c0 < nc) {
            const double* As = Ag + (size_t)c0 * 16 + ka;
#pragma unroll
            for (int q = 0; q < 8; q++) cpa8(aBase[c0] + 64 * q, As + (size_t)(ra0 + 8 * q) * lda);
            if (BT) {
                const double* Bs = Bg + (size_t)c0 * 16 + ka;
#pragma unroll
                for (int q = 0; q < 8; q++) cpa8(bBase[c0] + 64 * q, Bs + (size_t)(ra0 + 8 * q) * ldb);
            } else {
                const double* Bs = Bg + ((size_t)c0 * 16 + kb0) * ldb + cb;
#pragma unroll
                for (int q = 0; q < 8; q++) cpa8(bBase[c0] + 1024 * q, Bs + (size_t)(2 * q) * ldb);
            }
        }
        cp_commit();
    }
#pragma unroll 1
    for (int c = 0; c < nc; c++) {
        cp_wait<1>();
        __syncthreads();
        int pfc = c + 2;
        if (pfc < nc) {
            int nb = pfc - (pfc / 3) * 3;   // pfc % 3
            const double* As = Ag + (size_t)pfc * 16 + ka;
#pragma unroll
            for (int q = 0; q < 8; q++) cpa8(aBase[nb] + 64 * q, As + (size_t)(ra0 + 8 * q) * lda);
            if (BT) {
                const double* Bs = Bg + (size_t)pfc * 16 + ka;
#pragma unroll
                for (int q = 0; q < 8; q++) cpa8(bBase[nb] + 64 * q, Bs + (size_t)(ra0 + 8 * q) * ldb);
            } else {
                const double* Bs = Bg + ((size_t)pfc * 16 + kb0) * ldb + cb;
#pragma unroll
                for (int q = 0; q < 8; q++) cpa8(bBase[nb] + 1024 * q, Bs + (size_t)(2 * q) * ldb);
            }
        }
        cp_commit();
        int cur = c - (c / 3) * 3;          // c % 3
        const double (*pA)[64] = sA[cur];
        const double (*pB)[64] = sB[cur];
#pragma unroll
        for (int k = 0; k < 16; k++) {
            double2 av[4], bv[2];
#pragma unroll
            for (int p = 0; p < 4; p++) av[p] = *(const double2*)&pA[k][2 * ty + 16 * p];
#pragma unroll
            for (int q = 0; q < 2; q++) bv[q] = *(const double2*)&pB[k][2 * tx + 32 * q];
#pragma unroll
            for (int p = 0; p < 4; p++)
#pragma unroll
                for (int q = 0; q < 2; q++) {
                    acc[2 * p][2 * q]         += av[p].x * bv[q].x;
                    acc[2 * p][2 * q + 1]     += av[p].x * bv[q].y;
                    acc[2 * p + 1][2 * q]     += av[p].y * bv[q].x;
                    acc[2 * p + 1][2 * q + 1] += av[p].y * bv[q].y;
                }
        }
    }
    __syncthreads();
}
#define ROWOF(i) (2 * ty + 16 * ((i) >> 1) + ((i) & 1))
#define COLOF(j) (2 * tx + 32 * ((j) >> 1) + ((j) & 1))

// panel: L21 = A21 * Dinv^T
__global__ void __launch_bounds__(128) k_trsm(int kb) {
    int tx = threadIdx.x, ty = threadIdx.y, tid = ty * 16 + tx;
    int row0 = (kb + 1 + blockIdx.x) * NB;
    double acc[8][4] = {};
    gemm_pipe<1>(g_B + (size_t)row0 * NN + (size_t)kb * NB, NN,
                 &g_Dinv[kb][0][0], NB, 4, acc, tid, tx, ty);
#pragma unroll
    for (int i = 0; i < 8; i++)
#pragma unroll
        for (int j = 0; j < 4; j++)
            g_B[(size_t)(row0 + ROWOF(i)) * NN + kb * NB + COLOF(j)] = acc[i][j];
}

// trailing update, exact triangular 1D grid: C[tr][tc] -= P_tr * P_tc^T
__global__ void __launch_bounds__(128) k_syrk(int kb) {
    int b = blockIdx.x;
    float f = sqrtf(8.0f * (float)b + 1.0f);
    int tr = (int)((f - 1.0f) * 0.5f);
    while ((tr + 1) * (tr + 2) / 2 <= b) tr++;
    while (tr * (tr + 1) / 2 > b) tr--;
    int tc = b - tr * (tr + 1) / 2;
    int tx = threadIdx.x, ty = threadIdx.y, tid = ty * 16 + tx;
    int ra = (kb + 1 + tr) * NB, rb = (kb + 1 + tc) * NB;
    double acc[8][4] = {};
    gemm_pipe<1>(g_B + (size_t)ra * NN + (size_t)kb * NB, NN,
                 g_B + (size_t)rb * NN + (size_t)kb * NB, NN, 4, acc, tid, tx, ty);
#pragma unroll
    for (int i = 0; i < 8; i++)
#pragma unroll
        for (int j = 0; j < 4; j++)
            g_B[(size_t)(ra + ROWOF(i)) * NN + rb + COLOF(j)] -= acc[i][j];
}

// recursive trinv GEMM1: T = X22 * L21 (triangular k range; LPT: big iB first)
__global__ void __launch_bounds__(128) k_tg1(int t) {
    int H = 1 << t;
    int p = blockIdx.z, jB = blockIdx.x;
    int iB = H - 1 - blockIdx.y;
    int Jst = 2 * p * H, Ist = Jst + H;
    int gi = Ist + iB, gj = Jst + jB;
    size_t h = (size_t)H * NB;
    double* Tb = g_T + (size_t)p * h * h;
    int tx = threadIdx.x, ty = threadIdx.y, tid = ty * 16 + tx;
    double acc[8][4] = {};
    int nc = 4 * (iB + 1);
    gemm_pipe<0>(g_X + (size_t)(gi * NB) * NN + (size_t)Ist * NB, NN,
                 g_B + (size_t)(Ist * NB) * NN + (size_t)gj * NB, NN,
                 nc, acc, tid, tx, ty);
#pragma unroll
    for (int i = 0; i < 8; i++)
#pragma unroll
        for (int j = 0; j < 4; j++)
            Tb[(size_t)(iB * NB + ROWOF(i)) * h + jB * NB + COLOF(j)] = acc[i][j];
}

// recursive trinv GEMM2: X21 = -T * X11 (triangular k range)
__global__ void __launch_bounds__(128) k_tg2(int t) {
    int H = 1 << t;
    int p = blockIdx.z, iB = blockIdx.y, jB = blockIdx.x;
    int Jst = 2 * p * H, Ist = Jst + H;
    int gi = Ist + iB, gj = Jst + jB;
    size_t h = (size_t)H * NB;
    const double* Tb = g_T + (size_t)p * h * h;
    int tx = threadIdx.x, ty = threadIdx.y, tid = ty * 16 + tx;
    double acc[8][4] = {};
    int nc = 4 * (H - jB);
    gemm_pipe<0>(Tb + (size_t)(iB * NB) * h + (size_t)jB * NB, h,
                 g_X + (size_t)(gj * NB) * NN + (size_t)gj * NB, NN,
                 nc, acc, tid, tx, ty);
#pragma unroll
    for (int i = 0; i < 8; i++)
#pragma unroll
        for (int j = 0; j < 4; j++)
            g_X[(size_t)(gi * NB + ROWOF(i)) * NN + gj * NB + COLOF(j)] = -acc[i][j];
}

// diag(B^{-1})_i = sum_{k>=i} X[k][i]^2 minus deflation correction
__global__ void k_colsum() {
    int bj = blockIdx.x;
    int t = threadIdx.x;
    int c = t & 63, ro = t >> 6;
    double acc = 0.0;
    for (int r = bj * NB + ro; r < NN; r += 4) {
        double v = g_X[(size_t)r * NN + bj * NB + c];
        acc += v * v;
    }
    __shared__ double red[4][NB];
    red[ro][c] = acc;
    __syncthreads();
    if (t < NB) {
        double s = red[0][t] + red[1][t] + red[2][t] + red[3][t];
        g_diagf[bj * NB + t] = (float)(s - 1.0 / g_sumB);
    }
}

__global__ void k_edgesum(const int* __restrict__ V, const int* __restrict__ E) {
    int i = blockIdx.x * blockDim.x + threadIdx.x;
    if (i >= NNZ) return;
    atomicAdd(&g_edgesum[E[i]], g_diagf[V[i]]);
}

__global__ void k_probs(float* __restrict__ out) {
    int e = blockIdx.x * blockDim.x + threadIdx.x;
    if (e >= MEDG) return;
    float p = (g_counts[e] > 1) ? g_edgesum[e] : 0.0f;
    g_probs[e] = p;
    out[e] = p;
}

__global__ void k_topk(float* __restrict__ out) {
    int t = threadIdx.x;
    int e = blockIdx.x * 256 + t;
    float p = g_probs[e];
    int rank = 0;
    __shared__ float tile[1024];
    for (int base = 0; base < MEDG; base += 1024) {
        for (int q = 0; q < 4; q++) tile[t + q * 256] = g_probs[base + t + q * 256];
        __syncthreads();
        for (int q = 0; q < 1024; q++) {
            float v = tile[q];
            if (v > p || (v == p && (base + q) < e)) rank++;
        }
        __syncthreads();
    }
    float hard = (rank < KSEL) ? 1.0f : 0.0f;
    out[2 * MEDG + e] = hard;
    out[MEDG + e] = (hard - p) + p;
}

// ---------------- launch (single stream, no events, no allocations) ----------------
extern "C" void kernel_launch(void* const* d_in, const int* in_sizes, int n_in,
                              void* d_out, int out_size) {
    const int* V = (const int*)d_in[1];
    const int* E = (const int*)d_in[2];
    float* out = (float*)d_out;

    static int init = 0;
    const int DSM = 2 * NB * (NB + 1) * (int)sizeof(double);
    if (!init) {
        cudaFuncSetAttribute(k_potrf_dinv, cudaFuncAttributeMaxDynamicSharedMemorySize, DSM);
        init = 1;
    }

    dim3 thr(16, 8);
    k_zero<<<256, 256>>>();
    k_pairs<<<(NNZ + 255) / 256, 256>>>(V, E);
    k_scan<<<1, 1024>>>();
    k_nodelist<<<(NNZ + 255) / 256, 256>>>(V, E);
    k_fillB<<<2048, 256>>>();
    k_scatter<<<MEDG, 256>>>();
    k_sumB<<<1024, 256>>>();

    k_potrf_dinv<<<1, 256, DSM>>>(0);
    for (int kb = 0; kb < NT - 1; kb++) {
        int T = NT - 1 - kb;
        k_trsm<<<T, thr>>>(kb);
        k_syrk<<<T * (T + 1) / 2, thr>>>(kb);
        k_potrf_dinv<<<1, 256, DSM>>>(kb + 1);
    }

    for (int t = 0; t < 6; t++) {
        int H = 1 << t, P = 32 >> t;
        k_tg1<<<dim3(H, H, P), thr>>>(t);
        k_tg2<<<dim3(H, H, P), thr>>>(t);
    }

    k_colsum<<<NT, 256>>>();
    k_edgesum<<<(NNZ + 255) / 256, 256>>>(V, E);
    k_probs<<<MEDG / 256, 256>>>(out);
    k_topk<<<MEDG / 256, 256>>>(out);
}

// round 14
// speedup vs baseline: 1.2195x; 1.2195x over previous
#include <cuda_runtime.h>
#include <math.h>
#include <stdint.h>

static const int NN   = 4096;
static const int MEDG = 8192;
static const int NNZ  = 65536;
static const int NB   = 64;
static const int NT   = 64;   // NN/NB
static const int KSEL = 4096;
static const double SHIFT = 8.0;

// ---------------- static device scratch ----------------
static __device__ double   g_B[(size_t)NN * NN];      // matrix -> Cholesky L
static __device__ double   g_X[(size_t)NN * NN];      // L^{-1} (block lower)
static __device__ double   g_T[(size_t)2048 * 2048];  // recursive trinv temp
static __device__ double   g_Dinv[NT][NB][NB];        // inverses of diag blocks
static __device__ unsigned g_bitmap[((size_t)NN * MEDG) / 32];
static __device__ int      g_deg[NN];
static __device__ int      g_de[MEDG];
static __device__ int      g_off[MEDG + 1];
static __device__ int      g_cursor[MEDG];
static __device__ int      g_counts[MEDG];
static __device__ unsigned char g_owner[NNZ];
static __device__ int      g_nodelist[NNZ];
static __device__ float    g_deinv[MEDG];
static __device__ double   g_sumB;
static __device__ float    g_diagf[NN];
static __device__ float    g_edgesum[MEDG];
static __device__ float    g_probs[MEDG];

// ---------------- setup ----------------
__global__ void k_zero() {
    size_t i = (size_t)blockIdx.x * blockDim.x + threadIdx.x;
    size_t stride = (size_t)gridDim.x * blockDim.x;
    size_t nw = ((size_t)NN * MEDG) / 32;
    for (size_t w = i; w < nw; w += stride) g_bitmap[w] = 0u;
    for (size_t w = i; w < MEDG; w += stride) {
        g_de[w] = 0; g_cursor[w] = 0; g_counts[w] = 0; g_edgesum[w] = 0.0f;
    }
    for (size_t w = i; w < NN; w += stride) g_deg[w] = 0;
    if (i == 0) g_sumB = 0.0;
}

__global__ void k_pairs(const int* __restrict__ V, const int* __restrict__ E) {
    int i = blockIdx.x * blockDim.x + threadIdx.x;
    if (i >= NNZ) return;
    int v = V[i], e = E[i];
    atomicAdd(&g_counts[e], 1);
    size_t bit = (size_t)v * MEDG + e;
    unsigned mask = 1u << (bit & 31);
    unsigned old = atomicOr(&g_bitmap[bit >> 5], mask);
    if (!(old & mask)) {
        g_owner[i] = 1;
        atomicAdd(&g_de[e], 1);
        atomicAdd(&g_deg[v], 1);
    } else g_owner[i] = 0;
}

__global__ void k_scan() {
    __shared__ int part[1024];
    int t = threadIdx.x;
    int s = 0;
    for (int j = 0; j < 8; j++) s += g_de[t * 8 + j];
    part[t] = s;
    __syncthreads();
    if (t == 0) {
        int acc = 0;
        for (int i = 0; i < 1024; i++) { int tmp = part[i]; part[i] = acc; acc += tmp; }
        g_off[MEDG] = acc;
    }
    __syncthreads();
    int acc = part[t];
    for (int j = 0; j < 8; j++) { g_off[t * 8 + j] = acc; acc += g_de[t * 8 + j]; }
    for (int j = t; j < MEDG; j += 1024)
        g_deinv[j] = 1.0f / ((float)g_de[j] + 1e-8f);
}

__global__ void k_nodelist(const int* __restrict__ V, const int* __restrict__ E) {
    int i = blockIdx.x * blockDim.x + threadIdx.x;
    if (i >= NNZ || !g_owner[i]) return;
    int e = E[i];
    int pos = g_off[e] + atomicAdd(&g_cursor[e], 1);
    g_nodelist[pos] = V[i];
}

__global__ void k_fillB() {
    const double SON = SHIFT / (double)NN;
    size_t total = (size_t)NN * NN;
    size_t stride = (size_t)gridDim.x * blockDim.x;
    for (size_t idx = (size_t)blockIdx.x * blockDim.x + threadIdx.x; idx < total; idx += stride) {
        int i = (int)(idx >> 12), j = (int)(idx & (NN - 1));
        double v = SON;
        if (i == j) v += (double)g_deg[i] + (double)1e-3f;
        g_B[idx] = v;
    }
}

__global__ void k_scatter() {
    int e = blockIdx.x;
    int d = g_de[e];
    if (d == 0) return;
    int off = g_off[e];
    double w = -(double)g_deinv[e];
    for (int t = threadIdx.x; t < d * d; t += blockDim.x) {
        int u = g_nodelist[off + t / d];
        int v = g_nodelist[off + t % d];
        atomicAdd(&g_B[(size_t)u * NN + v], w);
    }
}

__global__ void k_sumB() {
    __shared__ double sh[256];
    double s = 0.0;
    size_t total = (size_t)NN * NN;
    size_t stride = (size_t)gridDim.x * blockDim.x;
    for (size_t idx = (size_t)blockIdx.x * blockDim.x + threadIdx.x; idx < total; idx += stride)
        s += g_B[idx];
    sh[threadIdx.x] = s;
    __syncthreads();
    for (int o = 128; o; o >>= 1) { if (threadIdx.x < o) sh[threadIdx.x] += sh[threadIdx.x + o]; __syncthreads(); }
    if (threadIdx.x == 0) atomicAdd(&g_sumB, sh[0]);
}

// ---------------- Cholesky diag block: factor + triangular inverse ----------------
__global__ void k_potrf_dinv(int kb) {
    extern __shared__ double sh[];
    double (*a)[NB + 1]    = (double (*)[NB + 1])sh;
    double (*minv)[NB + 1] = (double (*)[NB + 1])(sh + NB * (NB + 1));
    __shared__ double red[4][NB];
    int t = threadIdx.x;
    size_t base = ((size_t)kb * NB) * NN + (size_t)kb * NB;
    for (int idx = t; idx < NB * NB; idx += 256) {
        int r = idx >> 6, c = idx & 63;
        a[r][c] = g_B[base + (size_t)r * NN + c];
    }
    __syncthreads();
    for (int j = 0; j < NB; j++) {
        if (t == 0) a[j][j] = sqrt(a[j][j]);
        __syncthreads();
        double piv = a[j][j];
        for (int r = j + 1 + t; r < NB; r += 256) a[r][j] /= piv;
        __syncthreads();
        int W = NB - 1 - j;
        for (int idx = t; idx < W * W; idx += 256) {
            int r = j + 1 + idx / W, c = j + 1 + idx % W;
            if (c <= r) a[r][c] -= a[r][j] * a[c][j];
        }
        __syncthreads();
    }
    for (int idx = t; idx < NB * NB; idx += 256) {
        int r = idx >> 6, c = idx & 63;
        if (c <= r) g_B[base + (size_t)r * NN + c] = a[r][c];
    }
    for (int idx = t; idx < NB * NB; idx += 256)
        minv[idx >> 6][idx & 63] = ((idx >> 6) == (idx & 63)) ? 1.0 : 0.0;
    __syncthreads();
    int c = t & 63, p = t >> 6;
    for (int r = 0; r < NB; r++) {
        double part = 0.0;
        for (int k = p; k < r; k += 4) part += a[r][k] * minv[k][c];
        red[p][c] = part;
        __syncthreads();
        if (t < NB) {
            double s2 = red[0][t] + red[1][t] + red[2][t] + red[3][t];
            minv[r][t] = (minv[r][t] - s2) / a[r][r];
        }
        __syncthreads();
    }
    size_t xbase = ((size_t)kb * NB) * NN + (size_t)kb * NB;
    for (int idx = t; idx < NB * NB; idx += 256) {
        int r = idx >> 6, cc = idx & 63;
        double v = minv[r][cc];
        g_Dinv[kb][r][cc] = v;
        g_X[xbase + (size_t)r * NN + cc] = v;
    }
}

// ---------------- cp.async helpers ----------------
__device__ __forceinline__ void cpa8(uint32_t dst, const double* src) {
    asm volatile("cp.async.ca.shared.global [%0], [%1], 8;" :: "r"(dst), "l"(src));
}
__device__ __forceinline__ void cp_commit() {
    asm volatile("cp.async.commit_group;");
}
template<int N>
__device__ __forceinline__ void cp_wait() {
    asm volatile("cp.async.wait_group %0;" :: "n"(N));
}

// ======== 64x64 core (128 thr, 8x4 micro, 2-stage cp.async, padding 66) ========
// (exact R6 configuration — proven 9.587 ms)
template<int BT>
__device__ __forceinline__ void gemm_pipe(
    const double* __restrict__ Ag, size_t lda,
    const double* __restrict__ Bg, size_t ldb,
    int nc, double acc[8][4], int tid, int tx, int ty)
{
    __shared__ double sA[2][16][66], sB[2][16][66];
    int ka = tid & 15, ra0 = tid >> 4;
    int kb0 = tid >> 6, cb = tid & 63;
    uint32_t aBase[2], bBase[2];
    aBase[0] = (uint32_t)__cvta_generic_to_shared(&sA[0][ka][ra0]);
    aBase[1] = (uint32_t)__cvta_generic_to_shared(&sA[1][ka][ra0]);
    if (BT) {
        bBase[0] = (uint32_t)__cvta_generic_to_shared(&sB[0][ka][ra0]);
        bBase[1] = (uint32_t)__cvta_generic_to_shared(&sB[1][ka][ra0]);
    } else {
        bBase[0] = (uint32_t)__cvta_generic_to_shared(&sB[0][kb0][cb]);
        bBase[1] = (uint32_t)__cvta_generic_to_shared(&sB[1][kb0][cb]);
    }
    {
        const double* As = Ag + ka;
#pragma unroll
        for (int q = 0; q < 8; q++) cpa8(aBase[0] + 64 * q, As + (size_t)(ra0 + 8 * q) * lda);
        if (BT) {
            const double* Bs = Bg + ka;
#pragma unroll
            for (int q = 0; q < 8; q++) cpa8(bBase[0] + 64 * q, Bs + (size_t)(ra0 + 8 * q) * ldb);
        } else {
            const double* Bs = Bg + (size_t)kb0 * ldb + cb;
#pragma unroll
            for (int q = 0; q < 8; q++) cpa8(bBase[0] + 1056 * q, Bs + (size_t)(2 * q) * ldb);
        }
        cp_commit();
    }
#pragma unroll 1
    for (int c = 0; c < nc; c++) {
        int cur = c & 1;
        bool pf = (c + 1 < nc);
        if (pf) {
            int nxt = cur ^ 1;
            const double* As = Ag + (size_t)(c + 1) * 16 + ka;
#pragma unroll
            for (int q = 0; q < 8; q++) cpa8(aBase[nxt] + 64 * q, As + (size_t)(ra0 + 8 * q) * lda);
            if (BT) {
                const double* Bs = Bg + (size_t)(c + 1) * 16 + ka;
#pragma unroll
                for (int q = 0; q < 8; q++) cpa8(bBase[nxt] + 64 * q, Bs + (size_t)(ra0 + 8 * q) * ldb);
            } else {
                const double* Bs = Bg + ((size_t)(c + 1) * 16 + kb0) * ldb + cb;
#pragma unroll
                for (int q = 0; q < 8; q++) cpa8(bBase[nxt] + 1056 * q, Bs + (size_t)(2 * q) * ldb);
            }
            cp_commit();
            cp_wait<1>();
        } else {
            cp_wait<0>();
        }
        __syncthreads();
        const double (*pA)[66] = sA[cur];
        const double (*pB)[66] = sB[cur];
#pragma unroll
        for (int k = 0; k < 16; k++) {
            double2 av[4], bv[2];
#pragma unroll
            for (int p = 0; p < 4; p++) av[p] = *(const double2*)&pA[k][2 * ty + 16 * p];
#pragma unroll
            for (int q = 0; q < 2; q++) bv[q] = *(const double2*)&pB[k][2 * tx + 32 * q];
#pragma unroll
            for (int p = 0; p < 4; p++)
#pragma unroll
                for (int q = 0; q < 2; q++) {
                    acc[2 * p][2 * q]         += av[p].x * bv[q].x;
                    acc[2 * p][2 * q + 1]     += av[p].x * bv[q].y;
                    acc[2 * p + 1][2 * q]     += av[p].y * bv[q].x;
                    acc[2 * p + 1][2 * q + 1] += av[p].y * bv[q].y;
                }
        }
        __syncthreads();
    }
}
#define ROWOF(i) (2 * ty + 16 * ((i) >> 1) + ((i) & 1))
#define COLOF(j) (2 * tx + 32 * ((j) >> 1) + ((j) & 1))

// panel: L21 = A21 * Dinv^T
__global__ void __launch_bounds__(128) k_trsm(int kb) {
    int tx = threadIdx.x, ty = threadIdx.y, tid = ty * 16 + tx;
    int row0 = (kb + 1 + blockIdx.x) * NB;
    double acc[8][4] = {};
    gemm_pipe<1>(g_B + (size_t)row0 * NN + (size_t)kb * NB, NN,
                 &g_Dinv[kb][0][0], NB, 4, acc, tid, tx, ty);
#pragma unroll
    for (int i = 0; i < 8; i++)
#pragma unroll
        for (int j = 0; j < 4; j++)
            g_B[(size_t)(row0 + ROWOF(i)) * NN + kb * NB + COLOF(j)] = acc[i][j];
}

// trailing update, exact triangular 1D grid: C[tr][tc] -= P_tr * P_tc^T
__global__ void __launch_bounds__(128) k_syrk(int kb) {
    int b = blockIdx.x;
    float f = sqrtf(8.0f * (float)b + 1.0f);
    int tr = (int)((f - 1.0f) * 0.5f);
    while ((tr + 1) * (tr + 2) / 2 <= b) tr++;
    while (tr * (tr + 1) / 2 > b) tr--;
    int tc = b - tr * (tr + 1) / 2;
    int tx = threadIdx.x, ty = threadIdx.y, tid = ty * 16 + tx;
    int ra = (kb + 1 + tr) * NB, rb = (kb + 1 + tc) * NB;
    double acc[8][4] = {};
    gemm_pipe<1>(g_B + (size_t)ra * NN + (size_t)kb * NB, NN,
                 g_B + (size_t)rb * NN + (size_t)kb * NB, NN, 4, acc, tid, tx, ty);
#pragma unroll
    for (int i = 0; i < 8; i++)
#pragma unroll
        for (int j = 0; j < 4; j++)
            g_B[(size_t)(ra + ROWOF(i)) * NN + rb + COLOF(j)] -= acc[i][j];
}

// recursive trinv GEMM1: T = X22 * L21 (triangular k range; LPT: big iB first)
__global__ void __launch_bounds__(128) k_tg1(int t) {
    int H = 1 << t;
    int p = blockIdx.z, jB = blockIdx.x;
    int iB = H - 1 - blockIdx.y;
    int Jst = 2 * p * H, Ist = Jst + H;
    int gi = Ist + iB, gj = Jst + jB;
    size_t h = (size_t)H * NB;
    double* Tb = g_T + (size_t)p * h * h;
    int tx = threadIdx.x, ty = threadIdx.y, tid = ty * 16 + tx;
    double acc[8][4] = {};
    int nc = 4 * (iB + 1);
    gemm_pipe<0>(g_X + (size_t)(gi * NB) * NN + (size_t)Ist * NB, NN,
                 g_B + (size_t)(Ist * NB) * NN + (size_t)gj * NB, NN,
                 nc, acc, tid, tx, ty);
#pragma unroll
    for (int i = 0; i < 8; i++)
#pragma unroll
        for (int j = 0; j < 4; j++)
            Tb[(size_t)(iB * NB + ROWOF(i)) * h + jB * NB + COLOF(j)] = acc[i][j];
}

// recursive trinv GEMM2: X21 = -T * X11 (triangular k range)
__global__ void __launch_bounds__(128) k_tg2(int t) {
    int H = 1 << t;
    int p = blockIdx.z, iB = blockIdx.y, jB = blockIdx.x;
    int Jst = 2 * p * H, Ist = Jst + H;
    int gi = Ist + iB, gj = Jst + jB;
    size_t h = (size_t)H * NB;
    const double* Tb = g_T + (size_t)p * h * h;
    int tx = threadIdx.x, ty = threadIdx.y, tid = ty * 16 + tx;
    double acc[8][4] = {};
    int nc = 4 * (H - jB);
    gemm_pipe<0>(Tb + (size_t)(iB * NB) * h + (size_t)jB * NB, h,
                 g_X + (size_t)(gj * NB) * NN + (size_t)gj * NB, NN,
                 nc, acc, tid, tx, ty);
#pragma unroll
    for (int i = 0; i < 8; i++)
#pragma unroll
        for (int j = 0; j < 4; j++)
            g_X[(size_t)(gi * NB + ROWOF(i)) * NN + gj * NB + COLOF(j)] = -acc[i][j];
}

// diag(B^{-1})_i = sum_{k>=i} X[k][i]^2 minus deflation correction
__global__ void k_colsum() {
    int bj = blockIdx.x;
    int t = threadIdx.x;
    int c = t & 63, ro = t >> 6;
    double acc = 0.0;
    for (int r = bj * NB + ro; r < NN; r += 4) {
        double v = g_X[(size_t)r * NN + bj * NB + c];
        acc += v * v;
    }
    __shared__ double red[4][NB];
    red[ro][c] = acc;
    __syncthreads();
    if (t < NB) {
        double s = red[0][t] + red[1][t] + red[2][t] + red[3][t];
        g_diagf[bj * NB + t] = (float)(s - 1.0 / g_sumB);
    }
}

__global__ void k_edgesum(const int* __restrict__ V, const int* __restrict__ E) {
    int i = blockIdx.x * blockDim.x + threadIdx.x;
    if (i >= NNZ) return;
    atomicAdd(&g_edgesum[E[i]], g_diagf[V[i]]);
}

__global__ void k_probs(float* __restrict__ out) {
    int e = blockIdx.x * blockDim.x + threadIdx.x;
    if (e >= MEDG) return;
    float p = (g_counts[e] > 1) ? g_edgesum[e] : 0.0f;
    g_probs[e] = p;
    out[e] = p;
}

__global__ void k_topk(float* __restrict__ out) {
    int t = threadIdx.x;
    int e = blockIdx.x * 256 + t;
    float p = g_probs[e];
    int rank = 0;
    __shared__ float tile[1024];
    for (int base = 0; base < MEDG; base += 1024) {
        for (int q = 0; q < 4; q++) tile[t + q * 256] = g_probs[base + t + q * 256];
        __syncthreads();
        for (int q = 0; q < 1024; q++) {
            float v = tile[q];
            if (v > p || (v == p && (base + q) < e)) rank++;
        }
        __syncthreads();
    }
    float hard = (rank < KSEL) ? 1.0f : 0.0f;
    out[2 * MEDG + e] = hard;
    out[MEDG + e] = (hard - p) + p;
}

// ---------------- launch (single stream, no events, no allocations) ----------------
extern "C" void kernel_launch(void* const* d_in, const int* in_sizes, int n_in,
                              void* d_out, int out_size) {
    const int* V = (const int*)d_in[1];
    const int* E = (const int*)d_in[2];
    float* out = (float*)d_out;

    static int init = 0;
    const int DSM = 2 * NB * (NB + 1) * (int)sizeof(double);
    if (!init) {
        cudaFuncSetAttribute(k_potrf_dinv, cudaFuncAttributeMaxDynamicSharedMemorySize, DSM);
        init = 1;
    }

    dim3 thr(16, 8);
    k_zero<<<256, 256>>>();
    k_pairs<<<(NNZ + 255) / 256, 256>>>(V, E);
    k_scan<<<1, 1024>>>();
    k_nodelist<<<(NNZ + 255) / 256, 256>>>(V, E);
    k_fillB<<<2048, 256>>>();
    k_scatter<<<MEDG, 256>>>();
    k_sumB<<<1024, 256>>>();

    k_potrf_dinv<<<1, 256, DSM>>>(0);
    for (int kb = 0; kb < NT - 1; kb++) {
        int T = NT - 1 - kb;
        k_trsm<<<T, thr>>>(kb);
        k_syrk<<<T * (T + 1) / 2, thr>>>(kb);
        k_potrf_dinv<<<1, 256, DSM>>>(kb + 1);
    }

    for (int t = 0; t < 6; t++) {
        int H = 1 << t, P = 32 >> t;
        k_tg1<<<dim3(H, H, P), thr>>>(t);
        k_tg2<<<dim3(H, H, P), thr>>>(t);
    }

    k_colsum<<<NT, 256>>>();
    k_edgesum<<<(NNZ + 255) / 256, 256>>>(V, E);
    k_probs<<<MEDG / 256, 256>>>(out);
    k_topk<<<MEDG / 256, 256>>>(out);
}